// round 1
// baseline (speedup 1.0000x reference)
#include <cuda_runtime.h>
#include <math.h>
#include <float.h>
#include <stdint.h>

#define BB 4
#define NSEQ 1024
#define DQ 256
#define HH 8
#define DH 32
#define NTOK (BB*NSEQ)          // 4096
#define QSCALE 0.17677669529663687f  // 32^-0.5

// scratch (allocation-free rule: __device__ globals)
__device__ float g_Q[NTOK*DQ];    // [bh][i][32]
__device__ float g_K[NTOK*DQ];    // [bh][j][32]
__device__ float g_V[NTOK*DQ];    // [bh][j][32]
__device__ float g_Sig[NTOK*DQ];  // [token][256] sigmoid gates
__device__ float g_O[NTOK*DQ];    // [token][256] attention out (pre-gate)

__device__ __forceinline__ unsigned f2tf(float x){
    unsigned u; asm("cvt.rna.tf32.f32 %0, %1;" : "=r"(u) : "f"(x)); return u;
}
__device__ __forceinline__ void mma_tf32(float c[4],
    unsigned a0, unsigned a1, unsigned a2, unsigned a3,
    unsigned b0, unsigned b1)
{
    asm volatile(
        "mma.sync.aligned.m16n8k8.row.col.f32.tf32.tf32.f32 "
        "{%0,%1,%2,%3},{%4,%5,%6,%7},{%8,%9},{%0,%1,%2,%3};"
        : "+f"(c[0]), "+f"(c[1]), "+f"(c[2]), "+f"(c[3])
        : "r"(a0), "r"(a1), "r"(a2), "r"(a3), "r"(b0), "r"(b1));
}

// ============================================================
// Kernel 1: projections. C[4096,1024] = x[4096,256] @ Wall^T
// col ranges: [0,256)=q (scaled), [256,512)=k, [512,768)=v, [768,1024)=gate
// ============================================================
__global__ __launch_bounds__(256) void proj_kernel(
    const float* __restrict__ x,
    const float* __restrict__ Wq, const float* __restrict__ Wkv,
    const float* __restrict__ Wg, const float* __restrict__ bg)
{
    __shared__ float Asm[64][36];
    __shared__ float Bsm[64][36];

    const int tid = threadIdx.x;
    const int m0 = blockIdx.y * 64;
    const int e0 = blockIdx.x * 64;

    const float* Wsel; int mode;
    if (e0 < 256)      { Wsel = Wq  + (size_t)e0 * 256;          mode = 0; }
    else if (e0 < 512) { Wsel = Wkv + (size_t)(e0 - 256) * 256;  mode = 1; }
    else if (e0 < 768) { Wsel = Wkv + (size_t)(e0 - 256) * 256;  mode = 2; }
    else               { Wsel = Wg  + (size_t)(e0 - 768) * 256;  mode = 3; }

    const int warp = tid >> 5, lane = tid & 31;
    const int wm = warp & 3, wn = warp >> 2;
    const int g = lane >> 2, t4 = lane & 3;

    float acc[4][4];
    #pragma unroll
    for (int nt = 0; nt < 4; nt++)
        #pragma unroll
        for (int i = 0; i < 4; i++) acc[nt][i] = 0.f;

    for (int k0 = 0; k0 < 256; k0 += 32) {
        #pragma unroll
        for (int it = tid; it < 512; it += 256) {
            int r = it >> 3, c4 = (it & 7) << 2;
            *(float4*)&Asm[r][c4] = *(const float4*)&x[(size_t)(m0 + r) * 256 + k0 + c4];
            *(float4*)&Bsm[r][c4] = *(const float4*)&Wsel[(size_t)r * 256 + k0 + c4];
        }
        __syncthreads();
        #pragma unroll
        for (int ks = 0; ks < 4; ks++) {
            unsigned a0 = f2tf(Asm[wm*16 + g    ][ks*8 + t4    ]);
            unsigned a1 = f2tf(Asm[wm*16 + 8 + g][ks*8 + t4    ]);
            unsigned a2 = f2tf(Asm[wm*16 + g    ][ks*8 + 4 + t4]);
            unsigned a3 = f2tf(Asm[wm*16 + 8 + g][ks*8 + 4 + t4]);
            #pragma unroll
            for (int nt = 0; nt < 4; nt++) {
                unsigned b0 = f2tf(Bsm[wn*32 + nt*8 + g][ks*8 + t4    ]);
                unsigned b1 = f2tf(Bsm[wn*32 + nt*8 + g][ks*8 + 4 + t4]);
                mma_tf32(acc[nt], a0, a1, a2, a3, b0, b1);
            }
        }
        __syncthreads();
    }

    // epilogue
    #pragma unroll
    for (int nt = 0; nt < 4; nt++) {
        #pragma unroll
        for (int i = 0; i < 4; i++) {
            int r = m0 + wm*16 + g + ((i >= 2) ? 8 : 0);
            int e = e0 + wn*32 + nt*8 + t4*2 + (i & 1);
            float v = acc[nt][i];
            int b = r >> 10, ii = r & 1023;
            if (mode == 0) {
                int h = e >> 5, d = e & 31;
                g_Q[(size_t)((b*8 + h)*1024 + ii)*32 + d] = v * QSCALE;
            } else if (mode == 1) {
                int ek = e - 256;
                g_K[(size_t)((b*8 + (ek >> 5))*1024 + ii)*32 + (ek & 31)] = v;
            } else if (mode == 2) {
                int ev = e - 512;
                g_V[(size_t)((b*8 + (ev >> 5))*1024 + ii)*32 + (ev & 31)] = v;
            } else {
                int eg = e - 768;
                float z = v + bg[eg];
                g_Sig[(size_t)r * 256 + eg] = 1.f / (1.f + __expf(-z));
            }
        }
    }
}

// ============================================================
// Kernel 2: flash attention with additive bias + mask.
// grid (16, 32): x = 64-row i-tile, y = bh. 256 threads, warps 4x2.
// ============================================================
__global__ __launch_bounds__(256) void attn_kernel(
    const float* __restrict__ bias, const float* __restrict__ mask)
{
    __shared__ float Ksm[64][36];
    __shared__ float Vsm[64][36];
    __shared__ float Ssm[64][65];
    __shared__ float s_alpha[64];
    __shared__ float s_l[64];
    __shared__ float s_cmask[64];

    const int tid = threadIdx.x, warp = tid >> 5, lane = tid & 31;
    const int wm = warp & 3, wn = warp >> 2;
    const int g = lane >> 2, t4 = lane & 3;
    const int bh = blockIdx.y, b = bh >> 3, h = bh & 7;
    const int i0 = blockIdx.x * 64;

    // Q fragments (constant across j loop)
    unsigned qa[4][4];
    {
        const int r0 = i0 + wm*16 + g, r1 = r0 + 8;
        #pragma unroll
        for (int ks = 0; ks < 4; ks++) {
            qa[ks][0] = f2tf(g_Q[(size_t)(bh*1024 + r0)*32 + ks*8 + t4    ]);
            qa[ks][1] = f2tf(g_Q[(size_t)(bh*1024 + r1)*32 + ks*8 + t4    ]);
            qa[ks][2] = f2tf(g_Q[(size_t)(bh*1024 + r0)*32 + ks*8 + 4 + t4]);
            qa[ks][3] = f2tf(g_Q[(size_t)(bh*1024 + r1)*32 + ks*8 + 4 + t4]);
        }
    }

    // softmax thread mapping: 4 threads per row
    const int srow = tid >> 2;          // 0..63
    const int scol = (tid & 3) * 16;    // column base
    const float rmask = mask[b*1024 + i0 + srow];
    const bool rok = rmask > 0.f;
    float m_run = -FLT_MAX, l_run = 0.f;

    float oacc[2][4];
    #pragma unroll
    for (int nt = 0; nt < 2; nt++)
        #pragma unroll
        for (int i = 0; i < 4; i++) oacc[nt][i] = 0.f;

    const float* bias_row = bias + ((size_t)(bh*1024 + i0 + srow)) * 1024 + scol;

    for (int jt = 0; jt < 16; jt++) {
        const int j0 = jt * 64;

        // prefetch bias into registers (coalesced LDG.128 x4)
        float bf[16];
        {
            const float* bp = bias_row + j0;
            #pragma unroll
            for (int u = 0; u < 4; u++) {
                float4 t = *(const float4*)(bp + u*4);
                bf[4*u+0] = t.x; bf[4*u+1] = t.y; bf[4*u+2] = t.z; bf[4*u+3] = t.w;
            }
        }

        // K/V tiles -> smem (contiguous 8KB each)
        #pragma unroll
        for (int it = tid; it < 512; it += 256) {
            int r = it >> 3, c4 = (it & 7) << 2;
            *(float4*)&Ksm[r][c4] = *(const float4*)&g_K[(size_t)(bh*1024 + j0 + r)*32 + c4];
            *(float4*)&Vsm[r][c4] = *(const float4*)&g_V[(size_t)(bh*1024 + j0 + r)*32 + c4];
        }
        if (tid < 16)
            *(float4*)&s_cmask[tid*4] = *(const float4*)&mask[b*1024 + j0 + tid*4];
        __syncthreads();

        // S = Q K^T
        float sc[4][4];
        #pragma unroll
        for (int nt = 0; nt < 4; nt++)
            #pragma unroll
            for (int i = 0; i < 4; i++) sc[nt][i] = 0.f;
        #pragma unroll
        for (int ks = 0; ks < 4; ks++) {
            #pragma unroll
            for (int nt = 0; nt < 4; nt++) {
                unsigned b0 = f2tf(Ksm[wn*32 + nt*8 + g][ks*8 + t4    ]);
                unsigned b1 = f2tf(Ksm[wn*32 + nt*8 + g][ks*8 + 4 + t4]);
                mma_tf32(sc[nt], qa[ks][0], qa[ks][1], qa[ks][2], qa[ks][3], b0, b1);
            }
        }
        // S fragments -> smem
        #pragma unroll
        for (int nt = 0; nt < 4; nt++) {
            int c0 = wn*32 + nt*8 + t4*2;
            Ssm[wm*16 + g    ][c0    ] = sc[nt][0];
            Ssm[wm*16 + g    ][c0 + 1] = sc[nt][1];
            Ssm[wm*16 + 8 + g][c0    ] = sc[nt][2];
            Ssm[wm*16 + 8 + g][c0 + 1] = sc[nt][3];
        }
        __syncthreads();

        // online softmax (fp32)
        {
            float sv[16];
            float mx = -FLT_MAX;
            #pragma unroll
            for (int u = 0; u < 16; u++) {
                float cm = s_cmask[scol + u];
                float s = (rok && cm > 0.f) ? (Ssm[srow][scol + u] + bf[u]) : -FLT_MAX;
                sv[u] = s;
                mx = fmaxf(mx, s);
            }
            mx = fmaxf(mx, __shfl_xor_sync(0xffffffffu, mx, 1));
            mx = fmaxf(mx, __shfl_xor_sync(0xffffffffu, mx, 2));
            float m_new = fmaxf(m_run, mx);
            float sum = 0.f;
            #pragma unroll
            for (int u = 0; u < 16; u++) {
                float p = __expf(sv[u] - m_new);
                sum += p;
                Ssm[srow][scol + u] = p;
            }
            sum += __shfl_xor_sync(0xffffffffu, sum, 1);
            sum += __shfl_xor_sync(0xffffffffu, sum, 2);
            float alpha = __expf(m_run - m_new);
            l_run = l_run * alpha + sum;
            m_run = m_new;
            if ((tid & 3) == 0) s_alpha[srow] = alpha;
        }
        __syncthreads();

        // rescale O accumulators, then O += P V
        {
            float a_lo = s_alpha[wm*16 + g];
            float a_hi = s_alpha[wm*16 + 8 + g];
            #pragma unroll
            for (int nt = 0; nt < 2; nt++) {
                oacc[nt][0] *= a_lo; oacc[nt][1] *= a_lo;
                oacc[nt][2] *= a_hi; oacc[nt][3] *= a_hi;
            }
            #pragma unroll
            for (int ks = 0; ks < 8; ks++) {
                unsigned p0 = f2tf(Ssm[wm*16 + g    ][ks*8 + t4    ]);
                unsigned p1 = f2tf(Ssm[wm*16 + 8 + g][ks*8 + t4    ]);
                unsigned p2 = f2tf(Ssm[wm*16 + g    ][ks*8 + 4 + t4]);
                unsigned p3 = f2tf(Ssm[wm*16 + 8 + g][ks*8 + 4 + t4]);
                #pragma unroll
                for (int nt = 0; nt < 2; nt++) {
                    unsigned b0 = f2tf(Vsm[ks*8 + t4    ][wn*16 + nt*8 + g]);
                    unsigned b1 = f2tf(Vsm[ks*8 + 4 + t4][wn*16 + nt*8 + g]);
                    mma_tf32(oacc[nt], p0, p1, p2, p3, b0, b1);
                }
            }
        }
        __syncthreads();
    }

    // finalize: divide by l, write O[token][h*32+d]
    if ((tid & 3) == 0) s_l[srow] = l_run;
    __syncthreads();
    {
        float il_lo = 1.f / s_l[wm*16 + g];
        float il_hi = 1.f / s_l[wm*16 + 8 + g];
        #pragma unroll
        for (int nt = 0; nt < 2; nt++) {
            #pragma unroll
            for (int i = 0; i < 4; i++) {
                int r = i0 + wm*16 + g + ((i >= 2) ? 8 : 0);
                int d = wn*16 + nt*8 + t4*2 + (i & 1);
                float il = (i >= 2) ? il_hi : il_lo;
                g_O[(size_t)(b*1024 + r)*256 + h*32 + d] = oacc[nt][i] * il;
            }
        }
    }
}

// ============================================================
// Kernel 3: out = (O .* Sig) @ Wo^T + bo
// ============================================================
__global__ __launch_bounds__(256) void out_kernel(
    const float* __restrict__ Wo, const float* __restrict__ bo,
    float* __restrict__ out)
{
    __shared__ float Asm[64][36];
    __shared__ float Bsm[64][36];

    const int tid = threadIdx.x;
    const int m0 = blockIdx.y * 64;
    const int e0 = blockIdx.x * 64;

    const int warp = tid >> 5, lane = tid & 31;
    const int wm = warp & 3, wn = warp >> 2;
    const int g = lane >> 2, t4 = lane & 3;

    float acc[4][4];
    #pragma unroll
    for (int nt = 0; nt < 4; nt++)
        #pragma unroll
        for (int i = 0; i < 4; i++) acc[nt][i] = 0.f;

    for (int k0 = 0; k0 < 256; k0 += 32) {
        #pragma unroll
        for (int it = tid; it < 512; it += 256) {
            int r = it >> 3, c4 = (it & 7) << 2;
            size_t ia = (size_t)(m0 + r) * 256 + k0 + c4;
            float4 o4 = *(const float4*)&g_O[ia];
            float4 s4 = *(const float4*)&g_Sig[ia];
            float4 a4; a4.x = o4.x*s4.x; a4.y = o4.y*s4.y; a4.z = o4.z*s4.z; a4.w = o4.w*s4.w;
            *(float4*)&Asm[r][c4] = a4;
            *(float4*)&Bsm[r][c4] = *(const float4*)&Wo[(size_t)(e0 + r) * 256 + k0 + c4];
        }
        __syncthreads();
        #pragma unroll
        for (int ks = 0; ks < 4; ks++) {
            unsigned a0 = f2tf(Asm[wm*16 + g    ][ks*8 + t4    ]);
            unsigned a1 = f2tf(Asm[wm*16 + 8 + g][ks*8 + t4    ]);
            unsigned a2 = f2tf(Asm[wm*16 + g    ][ks*8 + 4 + t4]);
            unsigned a3 = f2tf(Asm[wm*16 + 8 + g][ks*8 + 4 + t4]);
            #pragma unroll
            for (int nt = 0; nt < 4; nt++) {
                unsigned b0 = f2tf(Bsm[wn*32 + nt*8 + g][ks*8 + t4    ]);
                unsigned b1 = f2tf(Bsm[wn*32 + nt*8 + g][ks*8 + 4 + t4]);
                mma_tf32(acc[nt], a0, a1, a2, a3, b0, b1);
            }
        }
        __syncthreads();
    }

    #pragma unroll
    for (int nt = 0; nt < 4; nt++) {
        #pragma unroll
        for (int i = 0; i < 4; i++) {
            int r = m0 + wm*16 + g + ((i >= 2) ? 8 : 0);
            int e = e0 + wn*32 + nt*8 + t4*2 + (i & 1);
            out[(size_t)r * 256 + e] = acc[nt][i] + bo[e];
        }
    }
}

extern "C" void kernel_launch(void* const* d_in, const int* in_sizes, int n_in,
                              void* d_out, int out_size)
{
    const float* x    = (const float*)d_in[0];
    const float* mask = (const float*)d_in[1];
    const float* bias = (const float*)d_in[2];
    const float* Wq   = (const float*)d_in[3];
    const float* Wkv  = (const float*)d_in[4];
    const float* Wo   = (const float*)d_in[5];
    const float* bo   = (const float*)d_in[6];
    const float* Wg   = (const float*)d_in[7];
    const float* bg   = (const float*)d_in[8];
    float* out = (float*)d_out;

    proj_kernel<<<dim3(16, 64), 256>>>(x, Wq, Wkv, Wg, bg);
    attn_kernel<<<dim3(16, 32), 256>>>(bias, mask);
    out_kernel<<<dim3(4, 64), 256>>>(Wo, bo, out);
}

// round 7
// speedup vs baseline: 1.1916x; 1.1916x over previous
#include <cuda_runtime.h>
#include <math.h>
#include <float.h>
#include <stdint.h>

#define BB 4
#define NSEQ 1024
#define DQ 256
#define HH 8
#define DH 32
#define NTOK (BB*NSEQ)          // 4096
#define QSCALE 0.17677669529663687f  // 32^-0.5

typedef unsigned int u32;

// ---------------- device scratch (allocation-free rule) ----------------
// Fragment-order tf32 operands:
// Qf[bh][it16][wm4][ks4][lane32][slot4]
__device__ u32 Qf[32*16*4*4*32*4];
// Kf[bh][jt16][jb8][ks4][lane32][s2]
__device__ u32 Kf[32*16*8*4*32*2];
// Vf[bh][jt16][db4][ksj8][lane32][s2]
__device__ u32 Vf[32*16*4*8*32*2];
// Packed weights, fragment order: Wallf[eb128][ks32][lane32][s2], Wof[eb32][ks32][lane32][s2]
__device__ u32 Wallf[128*32*32*2];
__device__ u32 Wof[32*32*32*2];
__device__ float g_Sig[NTOK*DQ];   // [token][256]
__device__ float g_O[NTOK*DQ];     // [token][256]

__device__ __forceinline__ u32 f2tf(float x){
    u32 u; asm("cvt.rna.tf32.f32 %0, %1;" : "=r"(u) : "f"(x)); return u;
}
__device__ __forceinline__ void mma_tf32(float c[4],
    u32 a0, u32 a1, u32 a2, u32 a3, u32 b0, u32 b1)
{
    asm volatile(
        "mma.sync.aligned.m16n8k8.row.col.f32.tf32.tf32.f32 "
        "{%0,%1,%2,%3},{%4,%5,%6,%7},{%8,%9},{%0,%1,%2,%3};"
        : "+f"(c[0]), "+f"(c[1]), "+f"(c[2]), "+f"(c[3])
        : "r"(a0), "r"(a1), "r"(a2), "r"(a3), "r"(b0), "r"(b1));
}

// ============================================================
// Kernel 0: repack weights into fragment order (tf32 bits)
// ============================================================
__global__ __launch_bounds__(256) void repack_kernel(
    const float* __restrict__ Wq, const float* __restrict__ Wkv,
    const float* __restrict__ Wg, const float* __restrict__ Wo)
{
    int i = blockIdx.x * 256 + threadIdx.x;
    if (i < 128*32*32*2) {
        int w = i;
        int s = w & 1, lane = (w >> 1) & 31, ks = (w >> 6) & 31, eb = w >> 11;
        int e = eb*8 + (lane >> 2);
        int c = ks*8 + s*4 + (lane & 3);
        float v;
        if (e < 256)      v = Wq[e*256 + c];
        else if (e < 768) v = Wkv[(e-256)*256 + c];
        else              v = Wg[(e-768)*256 + c];
        Wallf[w] = f2tf(v);
    } else {
        int w = i - 128*32*32*2;
        if (w < 32*32*32*2) {
            int s = w & 1, lane = (w >> 1) & 31, ks = (w >> 6) & 31, eb = w >> 11;
            int e = eb*8 + (lane >> 2);
            int c = ks*8 + s*4 + (lane & 3);
            Wof[w] = f2tf(Wo[e*256 + c]);
        }
    }
}

// ============================================================
// Kernel 1: projections. C[4096,1024] = x[4096,256] @ Wall^T
// ============================================================
__global__ __launch_bounds__(256) void proj_kernel(
    const float* __restrict__ x, const float* __restrict__ bg)
{
    __shared__ u32 Af[4*4*32*4];
    __shared__ u32 Bf[8*4*32*2];

    const int tid = threadIdx.x;
    const int m0 = blockIdx.y * 64;
    const int e0 = blockIdx.x * 64;
    const int eb0 = e0 >> 3;

    const int warp = tid >> 5, lane = tid & 31;
    const int wm = warp & 3, wn = warp >> 2;
    const int g = lane >> 2, t4 = lane & 3;

    float acc[4][4];
    #pragma unroll
    for (int nt = 0; nt < 4; nt++)
        #pragma unroll
        for (int i = 0; i < 4; i++) acc[nt][i] = 0.f;

    for (int k0 = 0; k0 < 256; k0 += 32) {
        const int kb0 = k0 >> 3;
        // ---- load A (x tile 64x32) into fragment smem ----
        #pragma unroll
        for (int u = 0; u < 2; u++) {
            int it = tid + 256*u;
            int r = it >> 3, c4 = (it & 7) << 2;
            float4 xv = *(const float4*)&x[(size_t)(m0 + r)*256 + k0 + c4];
            int wmr = r >> 4, gr = r & 15, ks = c4 >> 3, lo4 = c4 & 7;
            int slot = (gr < 8) ? (lo4 ? 2 : 0) : (lo4 ? 3 : 1);
            int lane0 = (gr & 7) * 4;
            u32* dst = &Af[((wmr*4 + ks)*32 + lane0)*4 + slot];
            dst[0]  = f2tf(xv.x);
            dst[4]  = f2tf(xv.y);
            dst[8]  = f2tf(xv.z);
            dst[12] = f2tf(xv.w);
        }
        // ---- load B (Wallf chunk) linear copy ----
        #pragma unroll
        for (int u = 0; u < 2; u++) {
            int i4 = tid + 256*u;              // 512 uint4 total
            int chunk = i4 >> 4, w16 = i4 & 15;
            int ebp = chunk >> 2, ksl = chunk & 3;
            const u32* src = &Wallf[(((eb0 + ebp)*32 + kb0 + ksl)*32)*2 + w16*4];
            *(uint4*)&Bf[i4*4] = *(const uint4*)src;
        }
        __syncthreads();
        #pragma unroll
        for (int ks = 0; ks < 4; ks++) {
            uint4 av = *(const uint4*)&Af[((wm*4 + ks)*32 + lane)*4];
            #pragma unroll
            for (int nt = 0; nt < 4; nt++) {
                int nb = wn*4 + nt;
                uint2 bv = *(const uint2*)&Bf[((nb*4 + ks)*32 + lane)*2];
                mma_tf32(acc[nt], av.x, av.y, av.z, av.w, bv.x, bv.y);
            }
        }
        __syncthreads();
    }

    // ---- epilogue: scatter into fragment-order Q/K/V + Sig ----
    #pragma unroll
    for (int nt = 0; nt < 4; nt++) {
        #pragma unroll
        for (int i = 0; i < 4; i++) {
            int r = m0 + wm*16 + g + ((i >= 2) ? 8 : 0);
            int e = e0 + wn*32 + nt*8 + t4*2 + (i & 1);
            float v = acc[nt][i];
            int b = r >> 10, ii = r & 1023;
            if (e < 256) {
                int h = e >> 5, d = e & 31, bh = b*8 + h;
                int it = ii >> 6, il = ii & 63, wmq = il >> 4, gq = il & 15;
                int dd = d & 7, ksq = d >> 3;
                int lq = (gq & 7)*4 + (dd & 3);
                int slot = (gq < 8) ? (dd < 4 ? 0 : 2) : (dd < 4 ? 1 : 3);
                Qf[((((size_t)(bh*16 + it)*4 + wmq)*4 + ksq)*32 + lq)*4 + slot] = f2tf(v * QSCALE);
            } else if (e < 512) {
                int ek = e - 256, h = ek >> 5, d = ek & 31, bh = b*8 + h;
                int jt = ii >> 6, jl = ii & 63, jb = jl >> 3, gk = jl & 7;
                int dd = d & 7, ksq = d >> 3;
                int lk = gk*4 + (dd & 3), s = (dd < 4) ? 0 : 1;
                Kf[((((size_t)(bh*16 + jt)*8 + jb)*4 + ksq)*32 + lk)*2 + s] = f2tf(v);
            } else if (e < 768) {
                int ev = e - 512, h = ev >> 5, d = ev & 31, bh = b*8 + h;
                int jt = ii >> 6, jl = ii & 63, ksj = jl >> 3, jj = jl & 7;
                int s = (jj < 4) ? 0 : 1;
                int lv = (d & 7)*4 + (jj & 3);
                int db = d >> 3;
                Vf[((((size_t)(bh*16 + jt)*4 + db)*8 + ksj)*32 + lv)*2 + s] = f2tf(v);
            } else {
                int eg = e - 768;
                float z = v + bg[eg];
                g_Sig[(size_t)r*256 + eg] = 1.f / (1.f + __expf(-z));
            }
        }
    }
}

// ============================================================
// Kernel 2: flash attention. grid (16 i-tiles, 32 bh), 256 thr.
// ============================================================
__global__ __launch_bounds__(256) void attn_kernel(
    const float* __restrict__ bias, const float* __restrict__ mask)
{
    __shared__ u32 Ks[2048];          // 8KB: [jb8][ks4][lane32][s2]
    __shared__ u32 Vs[2048];          // 8KB: [db4][ksj8][lane32][s2]
    __shared__ float Ssm[64][68];     // S then P(tf32 bits), pad 68
    __shared__ float s_alpha[64];
    __shared__ float s_l[64];
    __shared__ float s_cmask[64];

    const int tid = threadIdx.x, warp = tid >> 5, lane = tid & 31;
    const int wm = warp & 3, wn = warp >> 2;
    const int g = lane >> 2, t4 = lane & 3;
    const int bh = blockIdx.y, b = bh >> 3, h = bh & 7;
    const int it = blockIdx.x, i0 = it * 64;

    // ---- Q fragments (register-resident, tf32 bits) ----
    u32 qa[4][4];
    {
        const u32* qp = Qf + (((size_t)(bh*16 + it)*4 + wm)*4)*32*4;
        #pragma unroll
        for (int ks = 0; ks < 4; ks++) {
            uint4 t = *(const uint4*)(qp + (size_t)(ks*32 + lane)*4);
            qa[ks][0] = t.x; qa[ks][1] = t.y; qa[ks][2] = t.z; qa[ks][3] = t.w;
        }
    }

    // softmax mapping: thread = (row srow, quad q4) owns cols 16*q4..+15
    const int srow = tid >> 2, q4 = tid & 3, scol = q4 * 16;
    const bool rok = mask[b*1024 + i0 + srow] > 0.f;
    float m_run = -FLT_MAX, l_run = 0.f;

    float oacc[2][4];
    #pragma unroll
    for (int nt = 0; nt < 2; nt++)
        #pragma unroll
        for (int i = 0; i < 4; i++) oacc[nt][i] = 0.f;

    const float* bias_row = bias + ((size_t)(bh*1024 + i0 + srow))*1024 + scol;
    const u32* kgb = Kf + (size_t)(bh*16)*2048;
    const u32* vgb = Vf + (size_t)(bh*16)*2048;

    // prefetch tile 0 K/V + cmask into registers
    uint4 kr0, kr1, vr0, vr1; float4 cmv = make_float4(0,0,0,0);
    {
        const u32* kp = kgb; const u32* vp = vgb;
        kr0 = *(const uint4*)(kp + tid*4);
        kr1 = *(const uint4*)(kp + 1024 + tid*4);
        vr0 = *(const uint4*)(vp + tid*4);
        vr1 = *(const uint4*)(vp + 1024 + tid*4);
        if (tid < 16) cmv = *(const float4*)&mask[b*1024 + tid*4];
    }

    for (int jt = 0; jt < 16; jt++) {
        // stage K/V/cmask (prev PV finished: sync at loop end)
        *(uint4*)&Ks[tid*4] = kr0;  *(uint4*)&Ks[1024 + tid*4] = kr1;
        *(uint4*)&Vs[tid*4] = vr0;  *(uint4*)&Vs[1024 + tid*4] = vr1;
        if (tid < 16) *(float4*)&s_cmask[tid*4] = cmv;

        // bias prefetch for THIS tile (consumed in softmax)
        float bf[16];
        {
            const float* bp = bias_row + jt*64;
            #pragma unroll
            for (int u = 0; u < 4; u++) {
                float4 t = *(const float4*)(bp + u*4);
                bf[4*u+0] = t.x; bf[4*u+1] = t.y; bf[4*u+2] = t.z; bf[4*u+3] = t.w;
            }
        }
        __syncthreads();   // (a) K/V/cmask visible

        // prefetch next tile K/V into registers (overlaps compute)
        if (jt < 15) {
            const u32* kp = kgb + (size_t)(jt + 1)*2048;
            const u32* vp = vgb + (size_t)(jt + 1)*2048;
            kr0 = *(const uint4*)(kp + tid*4);
            kr1 = *(const uint4*)(kp + 1024 + tid*4);
            vr0 = *(const uint4*)(vp + tid*4);
            vr1 = *(const uint4*)(vp + 1024 + tid*4);
            if (tid < 16) cmv = *(const float4*)&mask[b*1024 + (jt+1)*64 + tid*4];
        }

        // ---- S = Q K^T ----
        float sc[4][4];
        #pragma unroll
        for (int nt = 0; nt < 4; nt++)
            #pragma unroll
            for (int i = 0; i < 4; i++) sc[nt][i] = 0.f;
        #pragma unroll
        for (int ks = 0; ks < 4; ks++) {
            #pragma unroll
            for (int nt = 0; nt < 4; nt++) {
                int jb = wn*4 + nt;
                uint2 bv = *(const uint2*)&Ks[((jb*4 + ks)*32 + lane)*2];
                mma_tf32(sc[nt], qa[ks][0], qa[ks][1], qa[ks][2], qa[ks][3], bv.x, bv.y);
            }
        }
        // S fragments -> Ssm (fp32, row-major)
        #pragma unroll
        for (int nt = 0; nt < 4; nt++) {
            int c0 = wn*32 + nt*8 + t4*2;
            *(float2*)&Ssm[wm*16 + g][c0]     = make_float2(sc[nt][0], sc[nt][1]);
            *(float2*)&Ssm[wm*16 + 8 + g][c0] = make_float2(sc[nt][2], sc[nt][3]);
        }
        __syncthreads();   // (b)

        // ---- online softmax (in-place: S fp32 -> P tf32 bits) ----
        {
            float sv[16]; float mx = -FLT_MAX;
            #pragma unroll
            for (int u4 = 0; u4 < 4; u4++) {
                float4 s4 = *(const float4*)&Ssm[srow][scol + u4*4];
                float ss[4] = {s4.x, s4.y, s4.z, s4.w};
                #pragma unroll
                for (int v = 0; v < 4; v++) {
                    int u = u4*4 + v;
                    float cm = s_cmask[scol + u];
                    float s = (rok && cm > 0.f) ? (ss[v] + bf[u]) : -FLT_MAX;
                    sv[u] = s; mx = fmaxf(mx, s);
                }
            }
            mx = fmaxf(mx, __shfl_xor_sync(0xffffffffu, mx, 1));
            mx = fmaxf(mx, __shfl_xor_sync(0xffffffffu, mx, 2));
            float m_new = fmaxf(m_run, mx);
            float sum = 0.f;
            #pragma unroll
            for (int u4 = 0; u4 < 4; u4++) {
                float4 pw;
                float p0 = __expf(sv[u4*4+0] - m_new);
                float p1 = __expf(sv[u4*4+1] - m_new);
                float p2 = __expf(sv[u4*4+2] - m_new);
                float p3 = __expf(sv[u4*4+3] - m_new);
                sum += (p0 + p1) + (p2 + p3);
                pw.x = __uint_as_float(f2tf(p0));
                pw.y = __uint_as_float(f2tf(p1));
                pw.z = __uint_as_float(f2tf(p2));
                pw.w = __uint_as_float(f2tf(p3));
                *(float4*)&Ssm[srow][scol + u4*4] = pw;
            }
            sum += __shfl_xor_sync(0xffffffffu, sum, 1);
            sum += __shfl_xor_sync(0xffffffffu, sum, 2);
            float alpha = __expf(m_run - m_new);
            l_run = l_run * alpha + sum;
            m_run = m_new;
            if (q4 == 0) s_alpha[srow] = alpha;
        }
        __syncthreads();   // (c)

        // ---- O = O*alpha + P V ----
        {
            float a_lo = s_alpha[wm*16 + g];
            float a_hi = s_alpha[wm*16 + 8 + g];
            #pragma unroll
            for (int nt = 0; nt < 2; nt++) {
                oacc[nt][0] *= a_lo; oacc[nt][1] *= a_lo;
                oacc[nt][2] *= a_hi; oacc[nt][3] *= a_hi;
            }
            #pragma unroll
            for (int ksj = 0; ksj < 8; ksj++) {
                u32 p0 = __float_as_uint(Ssm[wm*16 + g    ][ksj*8 + t4    ]);
                u32 p1 = __float_as_uint(Ssm[wm*16 + 8 + g][ksj*8 + t4    ]);
                u32 p2 = __float_as_uint(Ssm[wm*16 + g    ][ksj*8 + 4 + t4]);
                u32 p3 = __float_as_uint(Ssm[wm*16 + 8 + g][ksj*8 + 4 + t4]);
                #pragma unroll
                for (int ntd = 0; ntd < 2; ntd++) {
                    int db = wn*2 + ntd;
                    uint2 vv = *(const uint2*)&Vs[((db*8 + ksj)*32 + lane)*2];
                    mma_tf32(oacc[ntd], p0, p1, p2, p3, vv.x, vv.y);
                }
            }
        }
        __syncthreads();   // (d) protect Ks/Vs/Ssm for next tile
    }

    if (q4 == 0) s_l[srow] = l_run;
    __syncthreads();
    {
        float il_lo = 1.f / s_l[wm*16 + g];
        float il_hi = 1.f / s_l[wm*16 + 8 + g];
        #pragma unroll
        for (int nt = 0; nt < 2; nt++) {
            #pragma unroll
            for (int i = 0; i < 4; i++) {
                int r = i0 + wm*16 + g + ((i >= 2) ? 8 : 0);
                int d = wn*16 + nt*8 + t4*2 + (i & 1);
                float il = (i >= 2) ? il_hi : il_lo;
                g_O[(size_t)(b*1024 + r)*256 + h*32 + d] = oacc[nt][i] * il;
            }
        }
    }
}

// ============================================================
// Kernel 3: out = (O .* Sig) @ Wo^T + bo
// ============================================================
__global__ __launch_bounds__(256) void out_kernel(
    const float* __restrict__ bo, float* __restrict__ out)
{
    __shared__ u32 Af[4*4*32*4];
    __shared__ u32 Bf[8*4*32*2];

    const int tid = threadIdx.x;
    const int m0 = blockIdx.y * 64;
    const int e0 = blockIdx.x * 64;
    const int eb0 = e0 >> 3;

    const int warp = tid >> 5, lane = tid & 31;
    const int wm = warp & 3, wn = warp >> 2;
    const int g = lane >> 2, t4 = lane & 3;

    float acc[4][4];
    #pragma unroll
    for (int nt = 0; nt < 4; nt++)
        #pragma unroll
        for (int i = 0; i < 4; i++) acc[nt][i] = 0.f;

    for (int k0 = 0; k0 < 256; k0 += 32) {
        const int kb0 = k0 >> 3;
        #pragma unroll
        for (int u = 0; u < 2; u++) {
            int itx = tid + 256*u;
            int r = itx >> 3, c4 = (itx & 7) << 2;
            size_t ia = (size_t)(m0 + r)*256 + k0 + c4;
            float4 o4 = *(const float4*)&g_O[ia];
            float4 s4 = *(const float4*)&g_Sig[ia];
            int wmr = r >> 4, gr = r & 15, ks = c4 >> 3, lo4 = c4 & 7;
            int slot = (gr < 8) ? (lo4 ? 2 : 0) : (lo4 ? 3 : 1);
            int lane0 = (gr & 7) * 4;
            u32* dst = &Af[((wmr*4 + ks)*32 + lane0)*4 + slot];
            dst[0]  = f2tf(o4.x * s4.x);
            dst[4]  = f2tf(o4.y * s4.y);
            dst[8]  = f2tf(o4.z * s4.z);
            dst[12] = f2tf(o4.w * s4.w);
        }
        #pragma unroll
        for (int u = 0; u < 2; u++) {
            int i4 = tid + 256*u;
            int chunk = i4 >> 4, w16 = i4 & 15;
            int ebp = chunk >> 2, ksl = chunk & 3;
            const u32* src = &Wof[(((eb0 + ebp)*32 + kb0 + ksl)*32)*2 + w16*4];
            *(uint4*)&Bf[i4*4] = *(const uint4*)src;
        }
        __syncthreads();
        #pragma unroll
        for (int ks = 0; ks < 4; ks++) {
            uint4 av = *(const uint4*)&Af[((wm*4 + ks)*32 + lane)*4];
            #pragma unroll
            for (int nt = 0; nt < 4; nt++) {
                int nb = wn*4 + nt;
                uint2 bv = *(const uint2*)&Bf[((nb*4 + ks)*32 + lane)*2];
                mma_tf32(acc[nt], av.x, av.y, av.z, av.w, bv.x, bv.y);
            }
        }
        __syncthreads();
    }

    #pragma unroll
    for (int nt = 0; nt < 4; nt++) {
        #pragma unroll
        for (int i = 0; i < 4; i++) {
            int r = m0 + wm*16 + g + ((i >= 2) ? 8 : 0);
            int e = e0 + wn*32 + nt*8 + t4*2 + (i & 1);
            out[(size_t)r*256 + e] = acc[nt][i] + bo[e];
        }
    }
}

extern "C" void kernel_launch(void* const* d_in, const int* in_sizes, int n_in,
                              void* d_out, int out_size)
{
    const float* x    = (const float*)d_in[0];
    const float* mask = (const float*)d_in[1];
    const float* bias = (const float*)d_in[2];
    const float* Wq   = (const float*)d_in[3];
    const float* Wkv  = (const float*)d_in[4];
    const float* Wo   = (const float*)d_in[5];
    const float* bo   = (const float*)d_in[6];
    const float* Wg   = (const float*)d_in[7];
    const float* bg   = (const float*)d_in[8];
    float* out = (float*)d_out;

    // (262144 + 65536) words / 256 = 1280 blocks
    repack_kernel<<<1280, 256>>>(Wq, Wkv, Wg, Wo);
    proj_kernel<<<dim3(16, 64), 256>>>(x, bg);
    attn_kernel<<<dim3(16, 32), 256>>>(bias, mask);
    out_kernel<<<dim3(4, 64), 256>>>(bo, out);
}